// round 1
// baseline (speedup 1.0000x reference)
#include <cuda_runtime.h>
#include <math.h>

// Problem constants
#define Lc 8
#define Pc 8
#define Sc 128
#define Bc 16
#define Wc 768
#define Mc 64

// Scratch (allocation-free: __device__ globals)
__device__ float g_mp[Lc * Pc * Bc * Wc];   // [l,p,b,w]  max over s        (3 MB)
__device__ float g_score[Lc * Pc * Bc];     // raw score per (l,p,b)
__device__ float g_soft[Lc * Pc * Bc];      // softmaxed score
__device__ float g_sem[Lc * Bc * Wc];       // [l,b,w] sem_sum             (384 KB)

// ---------------------------------------------------------------------------
// Kernel 1: single streaming pass over embeds.
// grid = L*P*B = 1024 blocks, 768 threads.
// Each block owns one (l,p,b): 128 rows (s) x 768 floats (w), rows strided by
// B*W floats. Computes:
//   mp[w]    = max_s e[s,w]
//   score    = sum_{s,w} e[s,w] * w0[w] * w1[s]
// Thread layout: ssub = tid/192 handles s in {ssub, ssub+4, ...};
//                wq   = tid%192 handles float4 chunk w = 4*wq..4*wq+3.
// ---------------------------------------------------------------------------
__global__ __launch_bounds__(768, 2)
void k1_pass(const float* __restrict__ embeds,
             const float* __restrict__ w0,
             const float* __restrict__ w1)
{
    const int lpb = blockIdx.x;            // (l*P + p)*B + b
    const int b   = lpb & (Bc - 1);
    const int lp  = lpb >> 4;

    const float4* base = reinterpret_cast<const float4*>(
        embeds + ((size_t)lp * Sc * Bc + (size_t)b) * Wc);
    const int ROW4 = (Bc * Wc) / 4;        // row stride (s) in float4 = 3072

    const int tid  = threadIdx.x;
    const int ssub = tid / 192;            // 0..3
    const int wq   = tid % 192;            // float4 index within W

    const float4 w0v = __ldg(reinterpret_cast<const float4*>(w0) + wq);

    float4 mx = make_float4(-3.4e38f, -3.4e38f, -3.4e38f, -3.4e38f);
    float dot = 0.0f;

    #pragma unroll 4
    for (int s = ssub; s < Sc; s += 4) {
        float4 v = __ldg(base + (size_t)s * ROW4 + wq);
        float ws = __ldg(w1 + s);
        mx.x = fmaxf(mx.x, v.x);
        mx.y = fmaxf(mx.y, v.y);
        mx.z = fmaxf(mx.z, v.z);
        mx.w = fmaxf(mx.w, v.w);
        dot += (v.x * w0v.x + v.y * w0v.y + v.z * w0v.z + v.w * w0v.w) * ws;
    }

    __shared__ float4 smx[768];            // 12 KB
    __shared__ float  sred[24];
    smx[tid] = mx;

    // warp-reduce the dot
    #pragma unroll
    for (int o = 16; o > 0; o >>= 1)
        dot += __shfl_down_sync(0xffffffffu, dot, o);
    const int wid = tid >> 5, lid = tid & 31;
    if (lid == 0) sred[wid] = dot;
    __syncthreads();

    if (ssub == 0) {  // threads 0..191 finalize the max across 4 s-subsets
        float4 a = smx[wq];
        float4 c = smx[192 + wq];
        float4 d = smx[384 + wq];
        float4 e = smx[576 + wq];
        float4 r;
        r.x = fmaxf(fmaxf(a.x, c.x), fmaxf(d.x, e.x));
        r.y = fmaxf(fmaxf(a.y, c.y), fmaxf(d.y, e.y));
        r.z = fmaxf(fmaxf(a.z, c.z), fmaxf(d.z, e.z));
        r.w = fmaxf(fmaxf(a.w, c.w), fmaxf(d.w, e.w));
        reinterpret_cast<float4*>(g_mp)[(size_t)lpb * (Wc / 4) + wq] = r;
    }
    if (tid == 0) {
        float t = 0.0f;
        #pragma unroll
        for (int i = 0; i < 24; i++) t += sred[i];
        g_score[lpb] = t;
    }
}

// ---------------------------------------------------------------------------
// Kernel 2: sigmoid + softmax over the P axis, per (l,b). 1 block, 128 threads.
// score_raw already contains sum_{s,w} e*w0*w1; add b0*sum(w1) + b1 here.
// ---------------------------------------------------------------------------
__global__ void k2_softmax(const float* __restrict__ w1,
                           const float* __restrict__ b0,
                           const float* __restrict__ b1)
{
    const int tid = threadIdx.x;
    if (tid >= Lc * Bc) return;
    const int l = tid / Bc, b = tid % Bc;

    float sw1 = 0.0f;
    #pragma unroll 8
    for (int s = 0; s < Sc; s++) sw1 += __ldg(w1 + s);
    const float bias = b0[0] * sw1 + b1[0];

    float v[Pc];
    float mx = -3.4e38f;
    #pragma unroll
    for (int p = 0; p < Pc; p++) {
        float r = g_score[(l * Pc + p) * Bc + b] + bias;
        r = 1.0f / (1.0f + __expf(-r));     // sigmoid
        v[p] = r;
        mx = fmaxf(mx, r);
    }
    float sum = 0.0f;
    #pragma unroll
    for (int p = 0; p < Pc; p++) { v[p] = __expf(v[p] - mx); sum += v[p]; }
    const float inv = 1.0f / sum;
    #pragma unroll
    for (int p = 0; p < Pc; p++)
        g_soft[(l * Pc + p) * Bc + b] = v[p] * inv;
}

// ---------------------------------------------------------------------------
// Kernel 3: sem_sum[l,b,w] = sum_p mp[l,p,b,w] * soft[l,p,b]
// L*B*(W/4) = 24576 float4 threads -> 96 blocks x 256
// ---------------------------------------------------------------------------
__global__ void k3_sem()
{
    const int idx = blockIdx.x * blockDim.x + threadIdx.x;  // L*B*(W/4)
    const int w4  = idx % (Wc / 4);
    const int lb  = idx / (Wc / 4);
    const int b   = lb % Bc, l = lb / Bc;

    float4 acc = make_float4(0.f, 0.f, 0.f, 0.f);
    #pragma unroll
    for (int p = 0; p < Pc; p++) {
        const int lpb = (l * Pc + p) * Bc + b;
        const float s = g_soft[lpb];
        float4 m = reinterpret_cast<const float4*>(g_mp)[(size_t)lpb * (Wc / 4) + w4];
        acc.x += m.x * s; acc.y += m.y * s; acc.z += m.z * s; acc.w += m.w * s;
    }
    reinterpret_cast<float4*>(g_sem)[(size_t)lb * (Wc / 4) + w4] = acc;
}

// ---------------------------------------------------------------------------
// Kernel 4: out[b,m,w] = sum_l mask[b,l,m] * sem[l,b,w]
// B*M*(W/4) = 196608 float4 threads -> 768 blocks x 256. sem (384 KB) is
// L2-resident and reused 64x across m.
// ---------------------------------------------------------------------------
__global__ void k4_out(const float* __restrict__ mask,
                       float* __restrict__ out)
{
    const int idx = blockIdx.x * blockDim.x + threadIdx.x;  // B*M*(W/4)
    const int w4  = idx % (Wc / 4);
    const int bm  = idx / (Wc / 4);
    const int m   = bm % Mc, b = bm / Mc;

    float4 acc = make_float4(0.f, 0.f, 0.f, 0.f);
    #pragma unroll
    for (int l = 0; l < Lc; l++) {
        const float mk = __ldg(mask + ((size_t)b * Lc + l) * Mc + m);
        float4 sv = reinterpret_cast<const float4*>(g_sem)
                        [((size_t)(l * Bc + b)) * (Wc / 4) + w4];
        acc.x += mk * sv.x; acc.y += mk * sv.y;
        acc.z += mk * sv.z; acc.w += mk * sv.w;
    }
    reinterpret_cast<float4*>(out)[(size_t)bm * (Wc / 4) + w4] = acc;
}

// ---------------------------------------------------------------------------
extern "C" void kernel_launch(void* const* d_in, const int* in_sizes, int n_in,
                              void* d_out, int out_size)
{
    const float* embeds = (const float*)d_in[0];  // [L,P,S,B,W]
    const float* mask   = (const float*)d_in[1];  // [B,L,M]
    const float* w0     = (const float*)d_in[2];  // [1,W]
    const float* b0     = (const float*)d_in[3];  // [1]
    const float* w1     = (const float*)d_in[4];  // [1,S]
    const float* b1     = (const float*)d_in[5];  // [1]
    float* out          = (float*)d_out;          // [B,M,W]

    k1_pass<<<Lc * Pc * Bc, 768>>>(embeds, w0, w1);
    k2_softmax<<<1, 128>>>(w1, b0, b1);
    k3_sem<<<(Lc * Bc * (Wc / 4)) / 256, 256>>>();
    k4_out<<<(Bc * Mc * (Wc / 4)) / 256, 256>>>(mask, out);
}

// round 2
// speedup vs baseline: 1.1286x; 1.1286x over previous
#include <cuda_runtime.h>
#include <math.h>

#define Lc 8
#define Pc 8
#define Sc 128
#define Bc 16
#define Wc 768
#define Mc 64
#define W4 (Wc / 4)          // 192 float4 per W row
#define ROW4 ((Bc * Wc) / 4) // s-stride in float4 = 3072

// Scratch (allocation-free: __device__ globals)
__device__ float g_mp[Lc * Pc * Bc * Wc];   // [l,p,b,w]  max over s (3 MB)
__device__ float g_score[Lc * Pc * Bc];     // raw score per (l,p,b)
__device__ float g_sem[Lc * Bc * Wc];       // [l,b,w] sem_sum (384 KB)
__device__ float g_bias;                    // b0*sum(w1)+b1

// ---------------------------------------------------------------------------
// Kernel 1: single streaming pass over embeds. ONE wave.
// grid = L*P*B = 1024 blocks x 192 threads. Thread t owns float4 column t of
// its (l,p,b) tile and walks all 128 s-rows:
//   mx[t] = max_s e[s, 4t..4t+3]      (pure registers)
//   dot  += (e . w0) * w1[s]          (block-reduced at the end)
// ---------------------------------------------------------------------------
__global__ __launch_bounds__(192, 8)
void k1_pass(const float* __restrict__ embeds,
             const float* __restrict__ w0,
             const float* __restrict__ w1,
             const float* __restrict__ b0,
             const float* __restrict__ b1)
{
    __shared__ float sw1[Sc];
    __shared__ float sred[6];

    const int t = threadIdx.x;             // 0..191
    if (t < Sc) sw1[t] = __ldg(w1 + t);
    __syncthreads();

    const int lpb = blockIdx.x;            // (l*P + p)*B + b
    const int b   = lpb & (Bc - 1);
    const int lp  = lpb >> 4;

    const float4* base = reinterpret_cast<const float4*>(embeds)
                       + ((size_t)lp * Sc * Bc * Wc + (size_t)b * Wc) / 4 + t;

    const float4 w0v = __ldg(reinterpret_cast<const float4*>(w0) + t);

    float4 mx = make_float4(-3.4e38f, -3.4e38f, -3.4e38f, -3.4e38f);
    float dot = 0.0f;

    #pragma unroll 4
    for (int s = 0; s < Sc; s++) {
        float4 v = __ldg(base + (size_t)s * ROW4);
        mx.x = fmaxf(mx.x, v.x);
        mx.y = fmaxf(mx.y, v.y);
        mx.z = fmaxf(mx.z, v.z);
        mx.w = fmaxf(mx.w, v.w);
        dot += (v.x * w0v.x + v.y * w0v.y + v.z * w0v.z + v.w * w0v.w) * sw1[s];
    }

    // per-thread max -> direct coalesced store
    reinterpret_cast<float4*>(g_mp)[(size_t)lpb * W4 + t] = mx;

    // block-reduce the dot (6 warps)
    #pragma unroll
    for (int o = 16; o > 0; o >>= 1)
        dot += __shfl_down_sync(0xffffffffu, dot, o);
    if ((t & 31) == 0) sred[t >> 5] = dot;
    __syncthreads();
    if (t == 0) {
        float sum = sred[0] + sred[1] + sred[2] + sred[3] + sred[4] + sred[5];
        g_score[lpb] = sum;
    }

    // bias (once, block 0): b0 * sum(w1) + b1
    if (lpb == 0 && t == 1) {
        float s = 0.0f;
        #pragma unroll 8
        for (int i = 0; i < Sc; i++) s += sw1[i];
        g_bias = b0[0] * s + b1[0];
    }
}

// ---------------------------------------------------------------------------
// Kernel 2 (fused softmax + sem): sem[l,b,w] = sum_p mp[l,p,b,w] * soft[l,p,b]
// Each thread recomputes the 8-way sigmoid+softmax for its (l,b) locally.
// L*B*W4 = 24576 threads -> 96 blocks x 256.
// ---------------------------------------------------------------------------
__global__ void k3_sem()
{
    const int idx = blockIdx.x * blockDim.x + threadIdx.x;
    const int w4  = idx % W4;
    const int lb  = idx / W4;
    const int b   = lb & (Bc - 1);
    const int l   = lb >> 4;

    const float bias = g_bias;

    float v[Pc];
    float mxv = -3.4e38f;
    #pragma unroll
    for (int p = 0; p < Pc; p++) {
        float r = g_score[(l * Pc + p) * Bc + b] + bias;
        r = 1.0f / (1.0f + __expf(-r));          // sigmoid
        v[p] = r;
        mxv = fmaxf(mxv, r);
    }
    float sum = 0.0f;
    #pragma unroll
    for (int p = 0; p < Pc; p++) { v[p] = __expf(v[p] - mxv); sum += v[p]; }
    const float inv = 1.0f / sum;

    float4 acc = make_float4(0.f, 0.f, 0.f, 0.f);
    #pragma unroll
    for (int p = 0; p < Pc; p++) {
        const float s = v[p] * inv;
        float4 m = reinterpret_cast<const float4*>(g_mp)
                       [((size_t)(l * Pc + p) * Bc + b) * W4 + w4];
        acc.x += m.x * s; acc.y += m.y * s; acc.z += m.z * s; acc.w += m.w * s;
    }
    reinterpret_cast<float4*>(g_sem)[(size_t)lb * W4 + w4] = acc;
}

// ---------------------------------------------------------------------------
// Kernel 3: out[b,m,w] = sum_l mask[b,l,m] * sem[l,b,w]
// m-tiled x8: each thread caches sem[l=0..7] (8 float4 in regs) and emits
// 8 consecutive-group m outputs. B*(M/8)*W4 = 24576 threads -> 96 x 256.
// ---------------------------------------------------------------------------
__global__ __launch_bounds__(256)
void k4_out(const float* __restrict__ mask,
            float* __restrict__ out)
{
    const int idx = blockIdx.x * blockDim.x + threadIdx.x;
    const int w4  = idx % W4;
    const int bm  = idx / W4;          // b*(M/8) + mgrp
    const int mg  = bm & 7;
    const int b   = bm >> 3;

    float4 sv[Lc];
    #pragma unroll
    for (int l = 0; l < Lc; l++)
        sv[l] = reinterpret_cast<const float4*>(g_sem)
                    [((size_t)(l * Bc + b)) * W4 + w4];

    #pragma unroll
    for (int j = 0; j < 8; j++) {
        const int m = mg * 8 + j;
        float4 acc = make_float4(0.f, 0.f, 0.f, 0.f);
        #pragma unroll
        for (int l = 0; l < Lc; l++) {
            const float mk = __ldg(mask + ((size_t)b * Lc + l) * Mc + m);
            acc.x += mk * sv[l].x; acc.y += mk * sv[l].y;
            acc.z += mk * sv[l].z; acc.w += mk * sv[l].w;
        }
        reinterpret_cast<float4*>(out)[((size_t)b * Mc + m) * W4 + w4] = acc;
    }
}

// ---------------------------------------------------------------------------
extern "C" void kernel_launch(void* const* d_in, const int* in_sizes, int n_in,
                              void* d_out, int out_size)
{
    const float* embeds = (const float*)d_in[0];  // [L,P,S,B,W]
    const float* mask   = (const float*)d_in[1];  // [B,L,M]
    const float* w0     = (const float*)d_in[2];  // [1,W]
    const float* b0     = (const float*)d_in[3];  // [1]
    const float* w1     = (const float*)d_in[4];  // [1,S]
    const float* b1     = (const float*)d_in[5];  // [1]
    float* out          = (float*)d_out;          // [B,M,W]

    k1_pass<<<Lc * Pc * Bc, 192>>>(embeds, w0, w1, b0, b1);
    k3_sem<<<(Lc * Bc * W4) / 256, 256>>>();
    k4_out<<<(Bc * (Mc / 8) * W4) / 256, 256>>>(mask, out);
}

// round 3
// speedup vs baseline: 1.1786x; 1.0443x over previous
#include <cuda_runtime.h>
#include <math.h>

#define Lc 8
#define Pc 8
#define Sc 128
#define Bc 16
#define Wc 768
#define Mc 64
#define W4   (Wc / 4)            // 192 float4 per W row
#define ROW4 ((Bc * Wc) / 4)     // s-stride in float4 = 3072
#define NBLK (Lc * Pc * Bc)      // 1024
#define NTHR 192

// Scratch (allocation-free: __device__ globals)
__device__ float g_mp[Lc * Pc * Bc * Wc];   // [l,p,b,w] max over s (3 MB, L2-resident)
__device__ float g_score[Lc * Pc * Bc];     // raw score per (l,p,b)
__device__ float g_sem[Lc * Bc * Wc];       // [l,b,w] (384 KB, L2-resident)
__device__ float g_bias;                    // b0*sum(w1)+b1
__device__ unsigned g_bar_count;            // barrier arrival counter
__device__ unsigned g_bar_gen;              // barrier generation (monotonic)

// Generation-counting grid barrier. Safe: all NBLK CTAs are co-resident
// (192 thr x <=48 regs -> 7 CTAs/SM, 148*7=1036 >= 1024, single wave).
__device__ __forceinline__ void grid_barrier()
{
    __syncthreads();
    if (threadIdx.x == 0) {
        __threadfence();                                  // publish our stores
        unsigned gen = *((volatile unsigned*)&g_bar_gen); // read BEFORE arrive
        if (atomicAdd(&g_bar_count, 1) == NBLK - 1) {
            g_bar_count = 0;
            __threadfence();
            atomicAdd(&g_bar_gen, 1);                     // release
        } else {
            while (*((volatile unsigned*)&g_bar_gen) == gen) __nanosleep(64);
        }
    }
    __syncthreads();
}

// ---------------------------------------------------------------------------
// One fused persistent kernel: 1024 blocks x 192 threads, single wave.
// ---------------------------------------------------------------------------
__global__ __launch_bounds__(NTHR, 7)
void fused_kernel(const float* __restrict__ embeds,
                  const float* __restrict__ mask,
                  const float* __restrict__ w0,
                  const float* __restrict__ b0,
                  const float* __restrict__ w1,
                  const float* __restrict__ b1,
                  float* __restrict__ out)
{
    __shared__ float sw1[Sc];
    __shared__ float sred[6];

    const int t = threadIdx.x;              // 0..191
    if (t < Sc) sw1[t] = __ldg(w1 + t);
    __syncthreads();

    // ===================== Phase 1: stream embeds (402 MB) =================
    {
        const int lpb = blockIdx.x;          // (l*P+p)*B + b
        const int b   = lpb & (Bc - 1);
        const int lp  = lpb >> 4;

        const float4* base = reinterpret_cast<const float4*>(embeds)
                           + (size_t)lp * Sc * ROW4 + (size_t)b * W4 + t;
        const float4 w0v = __ldg(reinterpret_cast<const float4*>(w0) + t);

        float4 mx = make_float4(-3.4e38f, -3.4e38f, -3.4e38f, -3.4e38f);
        float dot0 = 0.0f, dot1 = 0.0f;

        #pragma unroll 8
        for (int s = 0; s < Sc; s += 2) {
            float4 v0 = __ldcs(base + (size_t)s * ROW4);
            float4 v1 = __ldcs(base + (size_t)(s + 1) * ROW4);
            mx.x = fmaxf(mx.x, fmaxf(v0.x, v1.x));
            mx.y = fmaxf(mx.y, fmaxf(v0.y, v1.y));
            mx.z = fmaxf(mx.z, fmaxf(v0.z, v1.z));
            mx.w = fmaxf(mx.w, fmaxf(v0.w, v1.w));
            dot0 += (v0.x * w0v.x + v0.y * w0v.y + v0.z * w0v.z + v0.w * w0v.w) * sw1[s];
            dot1 += (v1.x * w0v.x + v1.y * w0v.y + v1.z * w0v.z + v1.w * w0v.w) * sw1[s + 1];
        }

        reinterpret_cast<float4*>(g_mp)[(size_t)lpb * W4 + t] = mx;

        float dot = dot0 + dot1;
        #pragma unroll
        for (int o = 16; o > 0; o >>= 1)
            dot += __shfl_down_sync(0xffffffffu, dot, o);
        if ((t & 31) == 0) sred[t >> 5] = dot;
        __syncthreads();
        if (t == 0)
            g_score[lpb] = sred[0] + sred[1] + sred[2] + sred[3] + sred[4] + sred[5];

        if (lpb == 0 && t == 1) {
            float s = 0.0f;
            #pragma unroll 8
            for (int i = 0; i < Sc; i++) s += sw1[i];
            g_bias = b0[0] * s + b1[0];
        }
    }

    grid_barrier();

    // ===================== Phase 2: softmax + sem (L2-resident) ============
    {
        const int idx = blockIdx.x * NTHR + t;          // active: < 24576
        if (idx < Lc * Bc * W4) {
            const int w4 = idx % W4;
            const int lb = idx / W4;
            const int b  = lb & (Bc - 1);
            const int l  = lb >> 4;

            const float bias = g_bias;
            float v[Pc];
            float mxv = -3.4e38f;
            #pragma unroll
            for (int p = 0; p < Pc; p++) {
                float r = __ldcg(g_score + (l * Pc + p) * Bc + b) + bias;
                r = 1.0f / (1.0f + __expf(-r));          // sigmoid
                v[p] = r;
                mxv = fmaxf(mxv, r);
            }
            float sum = 0.0f;
            #pragma unroll
            for (int p = 0; p < Pc; p++) { v[p] = __expf(v[p] - mxv); sum += v[p]; }
            const float inv = 1.0f / sum;

            float4 acc = make_float4(0.f, 0.f, 0.f, 0.f);
            #pragma unroll
            for (int p = 0; p < Pc; p++) {
                const float s = v[p] * inv;
                float4 m = __ldcg(reinterpret_cast<const float4*>(g_mp)
                                  + ((size_t)(l * Pc + p) * Bc + b) * W4 + w4);
                acc.x += m.x * s; acc.y += m.y * s;
                acc.z += m.z * s; acc.w += m.w * s;
            }
            reinterpret_cast<float4*>(g_sem)[(size_t)lb * W4 + w4] = acc;
        }
    }

    grid_barrier();

    // ===================== Phase 3: out[b,m,w] = sum_l mask[b,l,m]*sem[l,b,w]
    {
        const int idx = blockIdx.x * NTHR + t;          // exactly 196608 items
        const int w4  = idx % W4;
        const int bm  = idx / W4;
        const int m   = bm % Mc;
        const int b   = bm / Mc;

        float4 acc = make_float4(0.f, 0.f, 0.f, 0.f);
        #pragma unroll
        for (int l = 0; l < Lc; l++) {
            const float mk = __ldg(mask + ((size_t)b * Lc + l) * Mc + m);
            float4 sv = __ldcg(reinterpret_cast<const float4*>(g_sem)
                               + ((size_t)(l * Bc + b)) * W4 + w4);
            acc.x += mk * sv.x; acc.y += mk * sv.y;
            acc.z += mk * sv.z; acc.w += mk * sv.w;
        }
        reinterpret_cast<float4*>(out)[(size_t)bm * W4 + w4] = acc;
    }
}

// ---------------------------------------------------------------------------
extern "C" void kernel_launch(void* const* d_in, const int* in_sizes, int n_in,
                              void* d_out, int out_size)
{
    const float* embeds = (const float*)d_in[0];  // [L,P,S,B,W]
    const float* mask   = (const float*)d_in[1];  // [B,L,M]
    const float* w0     = (const float*)d_in[2];  // [1,W]
    const float* b0     = (const float*)d_in[3];  // [1]
    const float* w1     = (const float*)d_in[4];  // [1,S]
    const float* b1     = (const float*)d_in[5];  // [1]
    float* out          = (float*)d_out;          // [B,M,W]

    fused_kernel<<<NBLK, NTHR>>>(embeds, mask, w0, b0, w1, b1, out);
}